// round 1
// baseline (speedup 1.0000x reference)
#include <cuda_runtime.h>
#include <math.h>

// DiffJPEG forward, fused single kernel.
// img: (16,3,512,512) f32, quality: int scalar, out: (16,3,512,512) f32.

#define IMG_W 512
#define IMG_H 512
#define BATCH 16
#define WPAD 513                    // odd stride -> conflict-free column access
#define CH_STRIDE (8 * WPAD)        // 4104 floats per channel-strip
#define SMEM_FLOATS (3 * CH_STRIDE) // 12312
#define SMEM_BYTES (2 * SMEM_FLOATS * 4) // 98496 bytes (ping-pong)

#define NTHREADS 512

__constant__ float c_lum[64] = {
    16, 11, 10, 16, 24, 40, 51, 61,
    12, 12, 14, 19, 26, 58, 60, 55,
    14, 13, 16, 24, 40, 57, 69, 56,
    14, 17, 22, 29, 51, 87, 80, 62,
    18, 22, 37, 56, 68, 109, 103, 77,
    24, 35, 55, 64, 81, 104, 113, 92,
    49, 64, 78, 87, 103, 121, 120, 101,
    72, 92, 95, 98, 112, 100, 103, 99
};
__constant__ float c_chrom[64] = {
    17, 18, 24, 47, 99, 99, 99, 99,
    18, 21, 26, 66, 99, 99, 99, 99,
    24, 26, 56, 99, 99, 99, 99, 99,
    47, 66, 99, 99, 99, 99, 99, 99,
    99, 99, 99, 99, 99, 99, 99, 99,
    99, 99, 99, 99, 99, 99, 99, 99,
    99, 99, 99, 99, 99, 99, 99, 99,
    99, 99, 99, 99, 99, 99, 99, 99
};

__global__ void __launch_bounds__(NTHREADS, 2)
jpeg_kernel(const float* __restrict__ img,
            const int* __restrict__ quality,
            float* __restrict__ out)
{
    extern __shared__ float sm[];
    float* Abuf = sm;
    float* Bbuf = sm + SMEM_FLOATS;
    __shared__ float M[64];     // DCT matrix
    __shared__ float qs[128];   // [0:64) lum scaled, [64:128) chrom scaled

    const int tid = threadIdx.x;

    // Build DCT matrix (double cos, then cast to f32, matching numpy)
    if (tid < 64) {
        int k = tid >> 3, n = tid & 7;
        double norm = (k == 0) ? sqrt(1.0 / 8.0) : sqrt(2.0 / 8.0);
        M[tid] = (float)(norm * cos(M_PI / 8.0 * ((double)n + 0.5) * (double)k));
    }
    // Build scaled quant tables from device-side quality
    if (tid >= 64 && tid < 192) {
        int i = tid - 64;
        int q = *quality;
        q = max(1, min(100, q));
        float scale = (q < 50) ? (5000.0f / (float)q) : (200.0f - 2.0f * (float)q);
        float base = (i < 64) ? c_lum[i] : c_chrom[i - 64];
        float v = (base * scale + 50.0f) * 0.01f;
        qs[i] = fminf(fmaxf(v, 1.0f), 255.0f);
    }

    const int b = blockIdx.x >> 6;          // batch
    const int strip = blockIdx.x & 63;      // 8-row strip index
    const int row0 = strip * 8;
    const size_t img_base = (size_t)b * 3 * IMG_H * IMG_W;

    // ---- Load + RGB->YCbCr into Abuf ----
    // 8 rows x 512 cols = 1024 float4-groups; 512 threads -> 2 groups each
    #pragma unroll
    for (int g = 0; g < 2; g++) {
        int idx = tid + g * NTHREADS;       // 0..1023
        int r = idx >> 7;                   // row within strip (128 groups/row)
        int col = (idx & 127) * 4;
        size_t off = img_base + (size_t)(row0 + r) * IMG_W + col;
        float4 r4 = *(const float4*)(img + off);
        float4 g4 = *(const float4*)(img + off + (size_t)IMG_H * IMG_W);
        float4 b4 = *(const float4*)(img + off + 2 * (size_t)IMG_H * IMG_W);
        float R[4] = {r4.x, r4.y, r4.z, r4.w};
        float G[4] = {g4.x, g4.y, g4.z, g4.w};
        float Bv[4] = {b4.x, b4.y, b4.z, b4.w};
        int sb = r * WPAD + col;
        #pragma unroll
        for (int j = 0; j < 4; j++) {
            float rr = R[j] * 255.0f, gg = G[j] * 255.0f, bb = Bv[j] * 255.0f;
            float y  =  0.299f  * rr + 0.587f  * gg + 0.114f  * bb;
            float cb = -0.1687f * rr - 0.3313f * gg + 0.5f    * bb + 128.0f;
            float cr =  0.5f    * rr - 0.4187f * gg - 0.0813f * bb + 128.0f;
            Abuf[0 * CH_STRIDE + sb + j] = y;
            Abuf[1 * CH_STRIDE + sb + j] = cb;
            Abuf[2 * CH_STRIDE + sb + j] = cr;
        }
    }
    __syncthreads();

    // Units: 3 ch * 64 blocks * 8 (rows or cols) = 1536; 512 threads -> 3 iters.
    // Decomposition u -> (inner=u&7, blk=(u>>3)&63, c=u>>9) is bank-conflict-free.

    // ---- Pass 1 (rows): T1 = (X - 128) @ M^T ;  A -> B ----
    #pragma unroll
    for (int it = 0; it < 3; it++) {
        int u = tid + it * NTHREADS;
        int r = u & 7, blk = (u >> 3) & 63, c = u >> 9;
        int base = c * CH_STRIDE + r * WPAD + blk * 8;
        float x[8];
        #pragma unroll
        for (int n = 0; n < 8; n++) x[n] = Abuf[base + n] - 128.0f;
        #pragma unroll
        for (int k = 0; k < 8; k++) {
            float s = 0.0f;
            #pragma unroll
            for (int n = 0; n < 8; n++) s += x[n] * M[k * 8 + n];
            Bbuf[base + k] = s;
        }
    }
    __syncthreads();

    // ---- Pass 2 (cols): D = M @ T1, then quantize ; B -> A ----
    #pragma unroll
    for (int it = 0; it < 3; it++) {
        int u = tid + it * NTHREADS;
        int l = u & 7, blk = (u >> 3) & 63, c = u >> 9;
        int base = c * CH_STRIDE + blk * 8 + l;
        float t[8];
        #pragma unroll
        for (int i = 0; i < 8; i++) t[i] = Bbuf[base + i * WPAD];
        // reference quirk: flat index (b*3 + c) < 16 -> luminance table
        const float* qt = ((b * 3 + c) < BATCH) ? qs : (qs + 64);
        #pragma unroll
        for (int k = 0; k < 8; k++) {
            float d = 0.0f;
            #pragma unroll
            for (int i = 0; i < 8; i++) d += M[k * 8 + i] * t[i];
            float q = qt[k * 8 + l];
            Abuf[base + k * WPAD] = rintf(d / q) * q;
        }
    }
    __syncthreads();

    // ---- Pass 3 (rows): T2 = Q @ M ; A -> B ----
    #pragma unroll
    for (int it = 0; it < 3; it++) {
        int u = tid + it * NTHREADS;
        int r = u & 7, blk = (u >> 3) & 63, c = u >> 9;
        int base = c * CH_STRIDE + r * WPAD + blk * 8;
        float x[8];
        #pragma unroll
        for (int n = 0; n < 8; n++) x[n] = Abuf[base + n];
        #pragma unroll
        for (int l = 0; l < 8; l++) {
            float s = 0.0f;
            #pragma unroll
            for (int n = 0; n < 8; n++) s += x[n] * M[n * 8 + l];
            Bbuf[base + l] = s;
        }
    }
    __syncthreads();

    // ---- Pass 4 (cols): R = M^T @ T2 + 128 ; B -> A ----
    #pragma unroll
    for (int it = 0; it < 3; it++) {
        int u = tid + it * NTHREADS;
        int l = u & 7, blk = (u >> 3) & 63, c = u >> 9;
        int base = c * CH_STRIDE + blk * 8 + l;
        float t[8];
        #pragma unroll
        for (int i = 0; i < 8; i++) t[i] = Bbuf[base + i * WPAD];
        #pragma unroll
        for (int k = 0; k < 8; k++) {
            float s = 0.0f;
            #pragma unroll
            for (int i = 0; i < 8; i++) s += M[i * 8 + k] * t[i];
            Abuf[base + k * WPAD] = s + 128.0f;
        }
    }
    __syncthreads();

    // ---- YCbCr->RGB, clip, store ----
    #pragma unroll
    for (int g = 0; g < 2; g++) {
        int idx = tid + g * NTHREADS;
        int r = idx >> 7;
        int col = (idx & 127) * 4;
        int sb = r * WPAD + col;
        float4 ro, go, bo;
        float* Rp = &ro.x; float* Gp = &go.x; float* Bp = &bo.x;
        #pragma unroll
        for (int j = 0; j < 4; j++) {
            float y  = Abuf[0 * CH_STRIDE + sb + j];
            float cb = Abuf[1 * CH_STRIDE + sb + j] - 128.0f;
            float cr = Abuf[2 * CH_STRIDE + sb + j] - 128.0f;
            float rr = y + 1.402f * cr;
            float gg = y - 0.34414f * cb - 0.71414f * cr;
            float bb = y + 1.772f * cb;
            Rp[j] = fminf(fmaxf(rr * (1.0f / 255.0f), 0.0f), 1.0f);
            Gp[j] = fminf(fmaxf(gg * (1.0f / 255.0f), 0.0f), 1.0f);
            Bp[j] = fminf(fmaxf(bb * (1.0f / 255.0f), 0.0f), 1.0f);
        }
        size_t off = img_base + (size_t)(row0 + r) * IMG_W + col;
        *(float4*)(out + off) = ro;
        *(float4*)(out + off + (size_t)IMG_H * IMG_W) = go;
        *(float4*)(out + off + 2 * (size_t)IMG_H * IMG_W) = bo;
    }
}

extern "C" void kernel_launch(void* const* d_in, const int* in_sizes, int n_in,
                              void* d_out, int out_size)
{
    const float* img = (const float*)d_in[0];
    const int* quality = (const int*)d_in[1];
    float* out = (float*)d_out;

    cudaFuncSetAttribute(jpeg_kernel,
                         cudaFuncAttributeMaxDynamicSharedMemorySize,
                         SMEM_BYTES);

    dim3 grid(BATCH * (IMG_H / 8));  // 16 * 64 = 1024 CTAs
    jpeg_kernel<<<grid, NTHREADS, SMEM_BYTES>>>(img, quality, out);
}

// round 2
// speedup vs baseline: 1.6684x; 1.6684x over previous
#include <cuda_runtime.h>
#include <math.h>

// DiffJPEG forward, fused single kernel, register-resident 8x8 blocks.
// img: (16,3,512,512) f32, quality: int scalar, out: (16,3,512,512) f32.

#define IMG_W 512
#define IMG_H 512
#define BATCH 16
#define NTHREADS 192
#define BLK_SLOT 68                      // 64 floats + 4 pad; 272B (16B aligned), 17-quad stride
#define NBLOCKS 192                      // 3 channels * 64 blocks per 8-row strip
#define SMEM_FLOATS (NBLOCKS * BLK_SLOT) // 13056
#define SMEM_BYTES (SMEM_FLOATS * 4)     // 52224

// Orthonormal 8-pt DCT-II butterfly constants (double-derived)
#define CA  0.35355339059327373f   // sqrt(1/8) = sqrt(2)/4
#define CB1 0.46193976625564337f   // 0.5*cos(pi/8)
#define CB3 0.19134171618254492f   // 0.5*cos(3pi/8)
#define CD1 0.49039264020161522f   // 0.5*cos(pi/16)
#define CD3 0.41573480615127262f   // 0.5*cos(3pi/16)
#define CD5 0.27778511650980114f   // 0.5*cos(5pi/16)
#define CD7 0.09754516100806413f   // 0.5*cos(7pi/16)

// Forward DCT-II, in place.  y = S3*S2*S1*x  (== M @ x for orthonormal M)
#define FDCT8(x0,x1,x2,x3,x4,x5,x6,x7) do {                                  \
    float e0=(x0)+(x7), e1=(x1)+(x6), e2=(x2)+(x5), e3=(x3)+(x4);            \
    float o0=(x0)-(x7), o1=(x1)-(x6), o2=(x2)-(x5), o3=(x3)-(x4);            \
    float ee0=e0+e3, ee1=e1+e2, eo0=e0-e3, eo1=e1-e2;                        \
    (x0) = CA*(ee0+ee1);                                                     \
    (x4) = CA*(ee0-ee1);                                                     \
    (x2) = CB1*eo0 + CB3*eo1;                                                \
    (x6) = CB3*eo0 - CB1*eo1;                                                \
    (x1) = CD1*o0 + CD3*o1 + CD5*o2 + CD7*o3;                                \
    (x3) = CD3*o0 - CD7*o1 - CD1*o2 - CD5*o3;                                \
    (x5) = CD5*o0 - CD1*o1 + CD7*o2 + CD3*o3;                                \
    (x7) = CD7*o0 - CD5*o1 + CD3*o2 - CD1*o3;                                \
} while(0)

// Inverse (DCT-III) = S1^T*S2^T*S3^T == M^T @ y
#define IDCT8(x0,x1,x2,x3,x4,x5,x6,x7) do {                                  \
    float ee0 = CA*((x0)+(x4)), ee1 = CA*((x0)-(x4));                        \
    float eo0 = CB1*(x2) + CB3*(x6), eo1 = CB3*(x2) - CB1*(x6);              \
    float o0 = CD1*(x1) + CD3*(x3) + CD5*(x5) + CD7*(x7);                    \
    float o1 = CD3*(x1) - CD7*(x3) - CD1*(x5) - CD5*(x7);                    \
    float o2 = CD5*(x1) - CD1*(x3) + CD7*(x5) + CD3*(x7);                    \
    float o3 = CD7*(x1) - CD5*(x3) + CD3*(x5) - CD1*(x7);                    \
    float e0=ee0+eo0, e3=ee0-eo0, e1=ee1+eo1, e2=ee1-eo1;                    \
    (x0)=e0+o0; (x7)=e0-o0; (x1)=e1+o1; (x6)=e1-o1;                          \
    (x2)=e2+o2; (x5)=e2-o2; (x3)=e3+o3; (x4)=e3-o3;                          \
} while(0)

__constant__ float c_lum[64] = {
    16, 11, 10, 16, 24, 40, 51, 61,
    12, 12, 14, 19, 26, 58, 60, 55,
    14, 13, 16, 24, 40, 57, 69, 56,
    14, 17, 22, 29, 51, 87, 80, 62,
    18, 22, 37, 56, 68, 109, 103, 77,
    24, 35, 55, 64, 81, 104, 113, 92,
    49, 64, 78, 87, 103, 121, 120, 101,
    72, 92, 95, 98, 112, 100, 103, 99
};
__constant__ float c_chrom[64] = {
    17, 18, 24, 47, 99, 99, 99, 99,
    18, 21, 26, 66, 99, 99, 99, 99,
    24, 26, 56, 99, 99, 99, 99, 99,
    47, 66, 99, 99, 99, 99, 99, 99,
    99, 99, 99, 99, 99, 99, 99, 99,
    99, 99, 99, 99, 99, 99, 99, 99,
    99, 99, 99, 99, 99, 99, 99, 99,
    99, 99, 99, 99, 99, 99, 99, 99
};

__global__ void __launch_bounds__(NTHREADS, 2)
jpeg_kernel(const float* __restrict__ img,
            const int* __restrict__ quality,
            float* __restrict__ out)
{
    extern __shared__ float sm[];       // block-major YCbCr: [(c*64+blk)*68 + r*8 + j]
    __shared__ float qs[128];           // [0:64) lum scaled, [64:128) chrom scaled

    const int tid = threadIdx.x;

    if (tid < 128) {
        int q = *quality;
        q = max(1, min(100, q));
        float scale = (q < 50) ? (5000.0f / (float)q) : (200.0f - 2.0f * (float)q);
        float base = (tid < 64) ? c_lum[tid] : c_chrom[tid - 64];
        float v = (base * scale + 50.0f) / 100.0f;
        qs[tid] = fminf(fmaxf(v, 1.0f), 255.0f);
    }

    const int b = blockIdx.x >> 6;       // batch
    const int strip = blockIdx.x & 63;   // 8-row strip
    const int row0 = strip * 8;
    const size_t img_base = (size_t)b * 3 * IMG_H * IMG_W;
    const size_t CH = (size_t)IMG_H * IMG_W;

    // ---- Load + RGB->YCbCr into block-major smem ----
    // 8 rows x 128 float4-groups = 1024 units
    #pragma unroll
    for (int g = 0; g < 6; g++) {
        int idx = tid + g * NTHREADS;
        if (idx < 1024) {
            int r = idx >> 7;
            int col = (idx & 127) << 2;
            size_t off = img_base + (size_t)(row0 + r) * IMG_W + col;
            float4 r4 = *(const float4*)(img + off);
            float4 g4 = *(const float4*)(img + off + CH);
            float4 b4 = *(const float4*)(img + off + 2 * CH);
            float4 y4, cb4, cr4;
            {
                const float* Rp = &r4.x; const float* Gp = &g4.x; const float* Bp = &b4.x;
                float* Yp = &y4.x; float* Cbp = &cb4.x; float* Crp = &cr4.x;
                #pragma unroll
                for (int j = 0; j < 4; j++) {
                    float rr = Rp[j] * 255.0f, gg = Gp[j] * 255.0f, bb = Bp[j] * 255.0f;
                    Yp[j]  =  0.299f  * rr + 0.587f  * gg + 0.114f  * bb;
                    Cbp[j] = -0.1687f * rr - 0.3313f * gg + 0.5f    * bb + 128.0f;
                    Crp[j] =  0.5f    * rr - 0.4187f * gg - 0.0813f * bb + 128.0f;
                }
            }
            int blk = col >> 3;
            int sbase = blk * BLK_SLOT + r * 8 + (col & 7);   // (col&7) in {0,4}
            *(float4*)(sm + sbase)                  = y4;
            *(float4*)(sm + 64 * BLK_SLOT + sbase)  = cb4;
            *(float4*)(sm + 128 * BLK_SLOT + sbase) = cr4;
        }
    }
    __syncthreads();

    // ---- Per-thread 8x8 block: DCT, quantize, IDCT, all in registers ----
    {
        const int c = tid / 64;          // channel (uniform per warp)
        const int blk = tid % 64;
        float* bp = sm + (c * 64 + blk) * BLK_SLOT;

        float x[8][8];
        #pragma unroll
        for (int w = 0; w < 16; w++) {
            float4 v = *(const float4*)(bp + w * 4);
            int rr = w >> 1, cc = (w & 1) * 4;
            x[rr][cc + 0] = v.x; x[rr][cc + 1] = v.y;
            x[rr][cc + 2] = v.z; x[rr][cc + 3] = v.w;
        }

        // forward: rows then cols   (== M @ (X) @ M^T)
        #pragma unroll
        for (int r = 0; r < 8; r++)
            FDCT8(x[r][0],x[r][1],x[r][2],x[r][3],x[r][4],x[r][5],x[r][6],x[r][7]);
        #pragma unroll
        for (int l = 0; l < 8; l++)
            FDCT8(x[0][l],x[1][l],x[2][l],x[3][l],x[4][l],x[5][l],x[6][l],x[7][l]);

        // -128 input shift commutes to DC only: DCT(X-128) = DCT(X) - 1024*E00
        x[0][0] -= 1024.0f;

        // quantize (reference quirk: flat index b*3+c < 16 selects luminance)
        const float* qt = ((b * 3 + c) < BATCH) ? qs : (qs + 64);
        #pragma unroll
        for (int k = 0; k < 8; k++) {
            #pragma unroll
            for (int l = 0; l < 8; l++) {
                float q = qt[k * 8 + l];
                x[k][l] = rintf(x[k][l] / q) * q;
            }
        }

        // +128 output shift commutes to DC: IDCT(T) + 128 = IDCT(T + 1024*E00)
        x[0][0] += 1024.0f;

        // inverse: cols then rows   (== M^T @ T @ M)
        #pragma unroll
        for (int l = 0; l < 8; l++)
            IDCT8(x[0][l],x[1][l],x[2][l],x[3][l],x[4][l],x[5][l],x[6][l],x[7][l]);
        #pragma unroll
        for (int r = 0; r < 8; r++)
            IDCT8(x[r][0],x[r][1],x[r][2],x[r][3],x[r][4],x[r][5],x[r][6],x[r][7]);

        #pragma unroll
        for (int w = 0; w < 16; w++) {
            int rr = w >> 1, cc = (w & 1) * 4;
            float4 v = make_float4(x[rr][cc + 0], x[rr][cc + 1],
                                   x[rr][cc + 2], x[rr][cc + 3]);
            *(float4*)(bp + w * 4) = v;
        }
    }
    __syncthreads();

    // ---- YCbCr->RGB, clip, store ----
    #pragma unroll
    for (int g = 0; g < 6; g++) {
        int idx = tid + g * NTHREADS;
        if (idx < 1024) {
            int r = idx >> 7;
            int col = (idx & 127) << 2;
            int blk = col >> 3;
            int sbase = blk * BLK_SLOT + r * 8 + (col & 7);
            float4 y4  = *(const float4*)(sm + sbase);
            float4 cb4 = *(const float4*)(sm + 64 * BLK_SLOT + sbase);
            float4 cr4 = *(const float4*)(sm + 128 * BLK_SLOT + sbase);
            float4 ro, go, bo;
            {
                const float* Yp = &y4.x; const float* Cbp = &cb4.x; const float* Crp = &cr4.x;
                float* Rp = &ro.x; float* Gp = &go.x; float* Bp = &bo.x;
                #pragma unroll
                for (int j = 0; j < 4; j++) {
                    float y  = Yp[j];
                    float cb = Cbp[j] - 128.0f;
                    float cr = Crp[j] - 128.0f;
                    float rr = y + 1.402f * cr;
                    float gg = y - 0.34414f * cb - 0.71414f * cr;
                    float bb = y + 1.772f * cb;
                    Rp[j] = fminf(fmaxf(rr * (1.0f / 255.0f), 0.0f), 1.0f);
                    Gp[j] = fminf(fmaxf(gg * (1.0f / 255.0f), 0.0f), 1.0f);
                    Bp[j] = fminf(fmaxf(bb * (1.0f / 255.0f), 0.0f), 1.0f);
                }
            }
            size_t off = img_base + (size_t)(row0 + r) * IMG_W + col;
            *(float4*)(out + off)          = ro;
            *(float4*)(out + off + CH)     = go;
            *(float4*)(out + off + 2 * CH) = bo;
        }
    }
}

extern "C" void kernel_launch(void* const* d_in, const int* in_sizes, int n_in,
                              void* d_out, int out_size)
{
    const float* img = (const float*)d_in[0];
    const int* quality = (const int*)d_in[1];
    float* out = (float*)d_out;

    cudaFuncSetAttribute(jpeg_kernel,
                         cudaFuncAttributeMaxDynamicSharedMemorySize,
                         SMEM_BYTES);

    dim3 grid(BATCH * (IMG_H / 8));  // 1024 CTAs
    jpeg_kernel<<<grid, NTHREADS, SMEM_BYTES>>>(img, quality, out);
}

// round 3
// speedup vs baseline: 2.6053x; 1.5615x over previous
#include <cuda_runtime.h>
#include <math.h>

// DiffJPEG forward: fused kernel, 8x8 block split across a thread PAIR.
// img: (16,3,512,512) f32, quality: int scalar, out: (16,3,512,512) f32.

#define IMG_W 512
#define IMG_H 512
#define BATCH 16
#define NTHREADS 384
#define NUNITS 192                        // 3 ch * 64 blocks per 8-row strip
// smem slot: per (unit, row-group a>>2): 36 floats (32 data + 4 pad)
// addr(unit,a,b) = unit*72 + (a>>2)*36 + (a&3)*8 + b   -> conflict-free float4
#define SMEM_FLOATS (NUNITS * 72)         // 13824
#define SMEM_BYTES  (SMEM_FLOATS * 4)     // 55296

// Orthonormal 8-pt DCT-II butterfly constants (double-derived)
#define CA  0.35355339059327373f
#define CB1 0.46193976625564337f
#define CB3 0.19134171618254492f
#define CD1 0.49039264020161522f
#define CD3 0.41573480615127262f
#define CD5 0.27778511650980114f
#define CD7 0.09754516100806413f

#define FDCT8(x0,x1,x2,x3,x4,x5,x6,x7) do {                                  \
    float e0=(x0)+(x7), e1=(x1)+(x6), e2=(x2)+(x5), e3=(x3)+(x4);            \
    float o0=(x0)-(x7), o1=(x1)-(x6), o2=(x2)-(x5), o3=(x3)-(x4);            \
    float ee0=e0+e3, ee1=e1+e2, eo0=e0-e3, eo1=e1-e2;                        \
    (x0) = CA*(ee0+ee1);                                                     \
    (x4) = CA*(ee0-ee1);                                                     \
    (x2) = CB1*eo0 + CB3*eo1;                                                \
    (x6) = CB3*eo0 - CB1*eo1;                                                \
    (x1) = CD1*o0 + CD3*o1 + CD5*o2 + CD7*o3;                                \
    (x3) = CD3*o0 - CD7*o1 - CD1*o2 - CD5*o3;                                \
    (x5) = CD5*o0 - CD1*o1 + CD7*o2 + CD3*o3;                                \
    (x7) = CD7*o0 - CD5*o1 + CD3*o2 - CD1*o3;                                \
} while(0)

#define IDCT8(x0,x1,x2,x3,x4,x5,x6,x7) do {                                  \
    float ee0 = CA*((x0)+(x4)), ee1 = CA*((x0)-(x4));                        \
    float eo0 = CB1*(x2) + CB3*(x6), eo1 = CB3*(x2) - CB1*(x6);              \
    float o0 = CD1*(x1) + CD3*(x3) + CD5*(x5) + CD7*(x7);                    \
    float o1 = CD3*(x1) - CD7*(x3) - CD1*(x5) - CD5*(x7);                    \
    float o2 = CD5*(x1) - CD1*(x3) + CD7*(x5) + CD3*(x7);                    \
    float o3 = CD7*(x1) - CD5*(x3) + CD3*(x5) - CD1*(x7);                    \
    float e0=ee0+eo0, e3=ee0-eo0, e1=ee1+eo1, e2=ee1-eo1;                    \
    (x0)=e0+o0; (x7)=e0-o0; (x1)=e1+o1; (x6)=e1-o1;                          \
    (x2)=e2+o2; (x5)=e2-o2; (x3)=e3+o3; (x4)=e3-o3;                          \
} while(0)

__constant__ float c_lum[64] = {
    16, 11, 10, 16, 24, 40, 51, 61,
    12, 12, 14, 19, 26, 58, 60, 55,
    14, 13, 16, 24, 40, 57, 69, 56,
    14, 17, 22, 29, 51, 87, 80, 62,
    18, 22, 37, 56, 68, 109, 103, 77,
    24, 35, 55, 64, 81, 104, 113, 92,
    49, 64, 78, 87, 103, 121, 120, 101,
    72, 92, 95, 98, 112, 100, 103, 99
};
__constant__ float c_chrom[64] = {
    17, 18, 24, 47, 99, 99, 99, 99,
    18, 21, 26, 66, 99, 99, 99, 99,
    24, 26, 56, 99, 99, 99, 99, 99,
    47, 66, 99, 99, 99, 99, 99, 99,
    99, 99, 99, 99, 99, 99, 99, 99,
    99, 99, 99, 99, 99, 99, 99, 99,
    99, 99, 99, 99, 99, 99, 99, 99,
    99, 99, 99, 99, 99, 99, 99, 99
};

__global__ void __launch_bounds__(NTHREADS, 2)
jpeg_kernel(const float* __restrict__ img,
            const int* __restrict__ quality,
            float* __restrict__ out)
{
    extern __shared__ float sm[];
    __shared__ float2 qs2[128];   // (q, 1/q): [0:64) lum, [64:128) chrom

    const int tid = threadIdx.x;

    if (tid < 128) {
        int q = *quality;
        q = max(1, min(100, q));
        float scale = (q < 50) ? (5000.0f / (float)q) : (200.0f - 2.0f * (float)q);
        float base = (tid < 64) ? c_lum[tid] : c_chrom[tid - 64];
        float v = (base * scale + 50.0f) / 100.0f;
        v = fminf(fmaxf(v, 1.0f), 255.0f);
        qs2[tid] = make_float2(v, 1.0f / v);  // exact IEEE reciprocal, once
    }

    const int b = blockIdx.x >> 6;
    const int strip = blockIdx.x & 63;
    const int row0 = strip * 8;
    const size_t img_base = (size_t)b * 3 * IMG_H * IMG_W;
    const size_t CH = (size_t)IMG_H * IMG_W;

    // ---- Phase A: load + RGB->YCbCr into block-slot smem ----
    #pragma unroll
    for (int g = 0; g < 3; g++) {
        int idx = tid + g * NTHREADS;
        if (idx < 1024) {
            int r = idx >> 7;
            int col = (idx & 127) << 2;
            size_t off = img_base + (size_t)(row0 + r) * IMG_W + col;
            float4 r4 = *(const float4*)(img + off);
            float4 g4 = *(const float4*)(img + off + CH);
            float4 b4 = *(const float4*)(img + off + 2 * CH);
            float4 y4, cb4, cr4;
            {
                const float* Rp = &r4.x; const float* Gp = &g4.x; const float* Bp = &b4.x;
                float* Yp = &y4.x; float* Cbp = &cb4.x; float* Crp = &cr4.x;
                #pragma unroll
                for (int j = 0; j < 4; j++) {
                    float rr = Rp[j] * 255.0f, gg = Gp[j] * 255.0f, bb = Bp[j] * 255.0f;
                    Yp[j]  =  0.299f  * rr + 0.587f  * gg + 0.114f  * bb;
                    Cbp[j] = -0.1687f * rr - 0.3313f * gg + 0.5f    * bb + 128.0f;
                    Crp[j] =  0.5f    * rr - 0.4187f * gg - 0.0813f * bb + 128.0f;
                }
            }
            int blk = col >> 3;
            int sb = blk * 72 + (r >> 2) * 36 + (r & 3) * 8 + (col & 7);
            *(float4*)(sm + sb)             = y4;
            *(float4*)(sm + 64 * 72 + sb)   = cb4;
            *(float4*)(sm + 128 * 72 + sb)  = cr4;
        }
    }
    __syncthreads();

    // ---- Phase B: thread pair per 8x8 block ----
    {
        const int unit = tid >> 1;          // 0..191 (c*64 + blk)
        const int half = tid & 1;           // 0: rows/cols 0-3, 1: 4-7
        const int c = unit >> 6;            // channel (uniform per warp)
        float* base = sm + unit * 72 + half * 36;

        float x[4][8];
        // load my 4 spatial rows
        #pragma unroll
        for (int i = 0; i < 4; i++) {
            float4 v0 = *(const float4*)(base + i * 8);
            float4 v1 = *(const float4*)(base + i * 8 + 4);
            x[i][0]=v0.x; x[i][1]=v0.y; x[i][2]=v0.z; x[i][3]=v0.w;
            x[i][4]=v1.x; x[i][5]=v1.y; x[i][6]=v1.z; x[i][7]=v1.w;
        }
        // row forward DCT
        #pragma unroll
        for (int i = 0; i < 4; i++)
            FDCT8(x[i][0],x[i][1],x[i][2],x[i][3],x[i][4],x[i][5],x[i][6],x[i][7]);

        __syncwarp();
        // store transposed: T1[r][l] -> slot(unit, a=l, b=r); my r's are one quad
        #pragma unroll
        for (int l = 0; l < 8; l++) {
            float4 v = make_float4(x[0][l], x[1][l], x[2][l], x[3][l]);
            *(float4*)(sm + unit * 72 + (l >> 2) * 36 + (l & 3) * 8 + half * 4) = v;
        }
        __syncwarp();

        // load transposed: y[j][r] = T1[r][l'], l' = half*4+j
        float y[4][8];
        #pragma unroll
        for (int j = 0; j < 4; j++) {
            float4 v0 = *(const float4*)(base + j * 8);
            float4 v1 = *(const float4*)(base + j * 8 + 4);
            y[j][0]=v0.x; y[j][1]=v0.y; y[j][2]=v0.z; y[j][3]=v0.w;
            y[j][4]=v1.x; y[j][5]=v1.y; y[j][6]=v1.z; y[j][7]=v1.w;
        }
        // column forward DCT (over r) -> y[j][k] = D[k][l']
        #pragma unroll
        for (int j = 0; j < 4; j++)
            FDCT8(y[j][0],y[j][1],y[j][2],y[j][3],y[j][4],y[j][5],y[j][6],y[j][7]);

        // -128 input shift commutes to DC: subtract 1024 (owned by half 0, j=0, k=0)
        if (half == 0) y[0][0] -= 1024.0f;

        // quantize: q index [k][l'], reciprocal multiply
        const float2* qt = ((b * 3 + c) < BATCH) ? qs2 : (qs2 + 64);
        #pragma unroll
        for (int j = 0; j < 4; j++) {
            int l = half * 4 + j;
            #pragma unroll
            for (int k = 0; k < 8; k++) {
                float2 q = qt[k * 8 + l];
                y[j][k] = rintf(y[j][k] * q.y) * q.x;
            }
        }

        // +128 output shift commutes to DC
        if (half == 0) y[0][0] += 1024.0f;

        // column inverse DCT -> y[j][i] = T2[i][l']
        #pragma unroll
        for (int j = 0; j < 4; j++)
            IDCT8(y[j][0],y[j][1],y[j][2],y[j][3],y[j][4],y[j][5],y[j][6],y[j][7]);

        __syncwarp();
        // store un-transposed: T2[i][l'] -> slot(unit, a=i, b=l'); my l's one quad
        #pragma unroll
        for (int i = 0; i < 8; i++) {
            float4 v = make_float4(y[0][i], y[1][i], y[2][i], y[3][i]);
            *(float4*)(sm + unit * 72 + (i >> 2) * 36 + (i & 3) * 8 + half * 4) = v;
        }
        __syncwarp();

        // load my 4 rows of T2, row inverse DCT -> spatial pixels
        #pragma unroll
        for (int i = 0; i < 4; i++) {
            float4 v0 = *(const float4*)(base + i * 8);
            float4 v1 = *(const float4*)(base + i * 8 + 4);
            x[i][0]=v0.x; x[i][1]=v0.y; x[i][2]=v0.z; x[i][3]=v0.w;
            x[i][4]=v1.x; x[i][5]=v1.y; x[i][6]=v1.z; x[i][7]=v1.w;
        }
        #pragma unroll
        for (int i = 0; i < 4; i++)
            IDCT8(x[i][0],x[i][1],x[i][2],x[i][3],x[i][4],x[i][5],x[i][6],x[i][7]);

        // store pixels back to my own slot (only I read it since last barrier)
        #pragma unroll
        for (int i = 0; i < 4; i++) {
            *(float4*)(base + i * 8)     = make_float4(x[i][0],x[i][1],x[i][2],x[i][3]);
            *(float4*)(base + i * 8 + 4) = make_float4(x[i][4],x[i][5],x[i][6],x[i][7]);
        }
    }
    __syncthreads();

    // ---- Phase C: YCbCr->RGB, clip, store ----
    #pragma unroll
    for (int g = 0; g < 3; g++) {
        int idx = tid + g * NTHREADS;
        if (idx < 1024) {
            int r = idx >> 7;
            int col = (idx & 127) << 2;
            int blk = col >> 3;
            int sb = blk * 72 + (r >> 2) * 36 + (r & 3) * 8 + (col & 7);
            float4 y4  = *(const float4*)(sm + sb);
            float4 cb4 = *(const float4*)(sm + 64 * 72 + sb);
            float4 cr4 = *(const float4*)(sm + 128 * 72 + sb);
            float4 ro, go, bo;
            {
                const float* Yp = &y4.x; const float* Cbp = &cb4.x; const float* Crp = &cr4.x;
                float* Rp = &ro.x; float* Gp = &go.x; float* Bp = &bo.x;
                #pragma unroll
                for (int j = 0; j < 4; j++) {
                    float y  = Yp[j];
                    float cb = Cbp[j] - 128.0f;
                    float cr = Crp[j] - 128.0f;
                    float rr = y + 1.402f * cr;
                    float gg = y - 0.34414f * cb - 0.71414f * cr;
                    float bb = y + 1.772f * cb;
                    Rp[j] = fminf(fmaxf(rr * (1.0f / 255.0f), 0.0f), 1.0f);
                    Gp[j] = fminf(fmaxf(gg * (1.0f / 255.0f), 0.0f), 1.0f);
                    Bp[j] = fminf(fmaxf(bb * (1.0f / 255.0f), 0.0f), 1.0f);
                }
            }
            size_t off = img_base + (size_t)(row0 + r) * IMG_W + col;
            *(float4*)(out + off)          = ro;
            *(float4*)(out + off + CH)     = go;
            *(float4*)(out + off + 2 * CH) = bo;
        }
    }
}

extern "C" void kernel_launch(void* const* d_in, const int* in_sizes, int n_in,
                              void* d_out, int out_size)
{
    const float* img = (const float*)d_in[0];
    const int* quality = (const int*)d_in[1];
    float* out = (float*)d_out;

    cudaFuncSetAttribute(jpeg_kernel,
                         cudaFuncAttributeMaxDynamicSharedMemorySize,
                         SMEM_BYTES);

    dim3 grid(BATCH * (IMG_H / 8));  // 1024 CTAs
    jpeg_kernel<<<grid, NTHREADS, SMEM_BYTES>>>(img, quality, out);
}

// round 4
// speedup vs baseline: 2.6240x; 1.0072x over previous
#include <cuda_runtime.h>
#include <math.h>

// DiffJPEG forward: fused kernel, 8x8 block split across a thread QUAD.
// img: (16,3,512,512) f32, quality: int scalar, out: (16,3,512,512) f32.

#define IMG_W 512
#define IMG_H 512
#define BATCH 16
#define NTHREADS 768
#define NUNITS 192                        // 3 ch * 64 blocks per 8-row strip
// smem slot: addr(unit,a,b) = unit*72 + (a>>2)*36 + (a&3)*8 + b
#define SMEM_FLOATS (NUNITS * 72)         // 13824
#define SMEM_BYTES  (SMEM_FLOATS * 4)     // 55296

#define MAGIC 12582912.0f                 // 1.5 * 2^23: round-to-nearest-even

// Orthonormal 8-pt DCT-II butterfly constants (double-derived)
#define CA  0.35355339059327373f
#define CB1 0.46193976625564337f
#define CB3 0.19134171618254492f
#define CD1 0.49039264020161522f
#define CD3 0.41573480615127262f
#define CD5 0.27778511650980114f
#define CD7 0.09754516100806413f

#define FDCT8(x0,x1,x2,x3,x4,x5,x6,x7) do {                                  \
    float e0=(x0)+(x7), e1=(x1)+(x6), e2=(x2)+(x5), e3=(x3)+(x4);            \
    float o0=(x0)-(x7), o1=(x1)-(x6), o2=(x2)-(x5), o3=(x3)-(x4);            \
    float ee0=e0+e3, ee1=e1+e2, eo0=e0-e3, eo1=e1-e2;                        \
    (x0) = CA*(ee0+ee1);                                                     \
    (x4) = CA*(ee0-ee1);                                                     \
    (x2) = CB1*eo0 + CB3*eo1;                                                \
    (x6) = CB3*eo0 - CB1*eo1;                                                \
    (x1) = CD1*o0 + CD3*o1 + CD5*o2 + CD7*o3;                                \
    (x3) = CD3*o0 - CD7*o1 - CD1*o2 - CD5*o3;                                \
    (x5) = CD5*o0 - CD1*o1 + CD7*o2 + CD3*o3;                                \
    (x7) = CD7*o0 - CD5*o1 + CD3*o2 - CD1*o3;                                \
} while(0)

#define IDCT8(x0,x1,x2,x3,x4,x5,x6,x7) do {                                  \
    float ee0 = CA*((x0)+(x4)), ee1 = CA*((x0)-(x4));                        \
    float eo0 = CB1*(x2) + CB3*(x6), eo1 = CB3*(x2) - CB1*(x6);              \
    float o0 = CD1*(x1) + CD3*(x3) + CD5*(x5) + CD7*(x7);                    \
    float o1 = CD3*(x1) - CD7*(x3) - CD1*(x5) - CD5*(x7);                    \
    float o2 = CD5*(x1) - CD1*(x3) + CD7*(x5) + CD3*(x7);                    \
    float o3 = CD7*(x1) - CD5*(x3) + CD3*(x5) - CD1*(x7);                    \
    float e0=ee0+eo0, e3=ee0-eo0, e1=ee1+eo1, e2=ee1-eo1;                    \
    (x0)=e0+o0; (x7)=e0-o0; (x1)=e1+o1; (x6)=e1-o1;                          \
    (x2)=e2+o2; (x5)=e2-o2; (x3)=e3+o3; (x4)=e3-o3;                          \
} while(0)

__constant__ float c_lum[64] = {
    16, 11, 10, 16, 24, 40, 51, 61,
    12, 12, 14, 19, 26, 58, 60, 55,
    14, 13, 16, 24, 40, 57, 69, 56,
    14, 17, 22, 29, 51, 87, 80, 62,
    18, 22, 37, 56, 68, 109, 103, 77,
    24, 35, 55, 64, 81, 104, 113, 92,
    49, 64, 78, 87, 103, 121, 120, 101,
    72, 92, 95, 98, 112, 100, 103, 99
};
__constant__ float c_chrom[64] = {
    17, 18, 24, 47, 99, 99, 99, 99,
    18, 21, 26, 66, 99, 99, 99, 99,
    24, 26, 56, 99, 99, 99, 99, 99,
    47, 66, 99, 99, 99, 99, 99, 99,
    99, 99, 99, 99, 99, 99, 99, 99,
    99, 99, 99, 99, 99, 99, 99, 99,
    99, 99, 99, 99, 99, 99, 99, 99,
    99, 99, 99, 99, 99, 99, 99, 99
};

__global__ void __launch_bounds__(NTHREADS, 2)
jpeg_kernel(const float* __restrict__ img,
            const int* __restrict__ quality,
            float* __restrict__ out)
{
    extern __shared__ float sm[];
    __shared__ float2 qs2[128];   // (q, 1/q): [0:64) lum, [64:128) chrom

    const int tid = threadIdx.x;

    if (tid < 128) {
        int q = *quality;
        q = max(1, min(100, q));
        float scale = (q < 50) ? (5000.0f / (float)q) : (200.0f - 2.0f * (float)q);
        float base = (tid < 64) ? c_lum[tid] : c_chrom[tid - 64];
        float v = (base * scale + 50.0f) / 100.0f;
        v = fminf(fmaxf(v, 1.0f), 255.0f);
        qs2[tid] = make_float2(v, 1.0f / v);
    }

    const int b = blockIdx.x >> 6;
    const int strip = blockIdx.x & 63;
    const int row0 = strip * 8;
    const size_t img_base = (size_t)b * 3 * IMG_H * IMG_W;
    const size_t CH = (size_t)IMG_H * IMG_W;

    // ---- Phase A: load + RGB->YCbCr (x255 folded) into block-slot smem ----
    #pragma unroll
    for (int g = 0; g < 2; g++) {
        int idx = tid + g * NTHREADS;
        if (idx < 1024) {
            int r = idx >> 7;
            int col = (idx & 127) << 2;
            size_t off = img_base + (size_t)(row0 + r) * IMG_W + col;
            float4 r4 = *(const float4*)(img + off);
            float4 g4 = *(const float4*)(img + off + CH);
            float4 b4 = *(const float4*)(img + off + 2 * CH);
            float4 y4, cb4, cr4;
            {
                const float* Rp = &r4.x; const float* Gp = &g4.x; const float* Bp = &b4.x;
                float* Yp = &y4.x; float* Cbp = &cb4.x; float* Crp = &cr4.x;
                #pragma unroll
                for (int j = 0; j < 4; j++) {
                    float R = Rp[j], G = Gp[j], B = Bp[j];
                    Yp[j]  = fmaf(76.245f, R, fmaf(149.685f, G, 29.07f * B));
                    Cbp[j] = fmaf(-43.0185f, R, fmaf(-84.4815f, G, fmaf(127.5f, B, 128.0f)));
                    Crp[j] = fmaf(127.5f, R, fmaf(-106.7685f, G, fmaf(-20.7315f, B, 128.0f)));
                }
            }
            int blk = col >> 3;
            int sb = blk * 72 + (r >> 2) * 36 + (r & 3) * 8 + (col & 7);
            *(float4*)(sm + sb)             = y4;
            *(float4*)(sm + 64 * 72 + sb)   = cb4;
            *(float4*)(sm + 128 * 72 + sb)  = cr4;
        }
    }
    __syncthreads();

    // ---- Phase B: thread quad per 8x8 block (2 rows / 2 cols each) ----
    {
        const int unit = tid >> 2;          // 0..191 (c*64 + blk)
        const int q = tid & 3;              // row-pair index
        const int c = unit >> 6;
        float* ub = sm + unit * 72;

        float x[2][8];
        // load my 2 spatial rows (a = 2q, 2q+1)
        #pragma unroll
        for (int i = 0; i < 2; i++) {
            int a = 2 * q + i;
            float* rp = ub + (a >> 2) * 36 + (a & 3) * 8;
            float4 v0 = *(const float4*)(rp);
            float4 v1 = *(const float4*)(rp + 4);
            x[i][0]=v0.x; x[i][1]=v0.y; x[i][2]=v0.z; x[i][3]=v0.w;
            x[i][4]=v1.x; x[i][5]=v1.y; x[i][6]=v1.z; x[i][7]=v1.w;
        }
        // row forward DCT
        #pragma unroll
        for (int i = 0; i < 2; i++)
            FDCT8(x[i][0],x[i][1],x[i][2],x[i][3],x[i][4],x[i][5],x[i][6],x[i][7]);

        __syncwarp();
        // store transposed T1[l][r]: my r's (2q,2q+1) are one float2
        #pragma unroll
        for (int l = 0; l < 8; l++) {
            *(float2*)(ub + (l >> 2) * 36 + (l & 3) * 8 + 2 * q)
                = make_float2(x[0][l], x[1][l]);
        }
        __syncwarp();

        // load my 2 transposed rows (cols l = 2q, 2q+1), contiguous over r
        float y[2][8];
        #pragma unroll
        for (int j = 0; j < 2; j++) {
            int l = 2 * q + j;
            float* rp = ub + (l >> 2) * 36 + (l & 3) * 8;
            float4 v0 = *(const float4*)(rp);
            float4 v1 = *(const float4*)(rp + 4);
            y[j][0]=v0.x; y[j][1]=v0.y; y[j][2]=v0.z; y[j][3]=v0.w;
            y[j][4]=v1.x; y[j][5]=v1.y; y[j][6]=v1.z; y[j][7]=v1.w;
        }
        // column forward DCT -> y[j][k] = D[k][2q+j]
        #pragma unroll
        for (int j = 0; j < 2; j++)
            FDCT8(y[j][0],y[j][1],y[j][2],y[j][3],y[j][4],y[j][5],y[j][6],y[j][7]);

        // -128 input shift commutes to DC only (owner: q=0, j=0, k=0)
        if (q == 0) y[0][0] -= 1024.0f;

        // quantize: reciprocal multiply + magic round-to-even (exact rint)
        const float2* qt = ((b * 3 + c) < BATCH) ? qs2 : (qs2 + 64);
        #pragma unroll
        for (int j = 0; j < 2; j++) {
            int l = 2 * q + j;
            #pragma unroll
            for (int k = 0; k < 8; k++) {
                float2 qv = qt[k * 8 + l];
                float t = y[j][k] * qv.y;
                t = __fadd_rn(__fadd_rn(t, MAGIC), -MAGIC);
                y[j][k] = t * qv.x;
            }
        }

        // +128 output shift commutes to DC
        if (q == 0) y[0][0] += 1024.0f;

        // column inverse DCT -> y[j][i] = T2[i][2q+j]
        #pragma unroll
        for (int j = 0; j < 2; j++)
            IDCT8(y[j][0],y[j][1],y[j][2],y[j][3],y[j][4],y[j][5],y[j][6],y[j][7]);

        __syncwarp();   // all lanes done reading T1 before overwriting with T2
        // store T2[i][l']: my l's (2q,2q+1) are one float2 per row i
        #pragma unroll
        for (int i = 0; i < 8; i++) {
            *(float2*)(ub + (i >> 2) * 36 + (i & 3) * 8 + 2 * q)
                = make_float2(y[0][i], y[1][i]);
        }
        __syncwarp();

        // load my 2 rows of T2, row inverse DCT -> spatial pixels
        #pragma unroll
        for (int i = 0; i < 2; i++) {
            int a = 2 * q + i;
            float* rp = ub + (a >> 2) * 36 + (a & 3) * 8;
            float4 v0 = *(const float4*)(rp);
            float4 v1 = *(const float4*)(rp + 4);
            x[i][0]=v0.x; x[i][1]=v0.y; x[i][2]=v0.z; x[i][3]=v0.w;
            x[i][4]=v1.x; x[i][5]=v1.y; x[i][6]=v1.z; x[i][7]=v1.w;
        }
        #pragma unroll
        for (int i = 0; i < 2; i++)
            IDCT8(x[i][0],x[i][1],x[i][2],x[i][3],x[i][4],x[i][5],x[i][6],x[i][7]);

        // pixel store targets exactly the T2 rows only THIS lane read -> no hazard
        #pragma unroll
        for (int i = 0; i < 2; i++) {
            int a = 2 * q + i;
            float* rp = ub + (a >> 2) * 36 + (a & 3) * 8;
            *(float4*)(rp)     = make_float4(x[i][0],x[i][1],x[i][2],x[i][3]);
            *(float4*)(rp + 4) = make_float4(x[i][4],x[i][5],x[i][6],x[i][7]);
        }
    }
    __syncthreads();

    // ---- Phase C: YCbCr->RGB, clip, store ----
    #pragma unroll
    for (int g = 0; g < 2; g++) {
        int idx = tid + g * NTHREADS;
        if (idx < 1024) {
            int r = idx >> 7;
            int col = (idx & 127) << 2;
            int blk = col >> 3;
            int sb = blk * 72 + (r >> 2) * 36 + (r & 3) * 8 + (col & 7);
            float4 y4  = *(const float4*)(sm + sb);
            float4 cb4 = *(const float4*)(sm + 64 * 72 + sb);
            float4 cr4 = *(const float4*)(sm + 128 * 72 + sb);
            float4 ro, go, bo;
            {
                const float* Yp = &y4.x; const float* Cbp = &cb4.x; const float* Crp = &cr4.x;
                float* Rp = &ro.x; float* Gp = &go.x; float* Bp = &bo.x;
                #pragma unroll
                for (int j = 0; j < 4; j++) {
                    float y  = Yp[j];
                    float cb = Cbp[j] - 128.0f;
                    float cr = Crp[j] - 128.0f;
                    float rr = y + 1.402f * cr;
                    float gg = y - 0.34414f * cb - 0.71414f * cr;
                    float bb = y + 1.772f * cb;
                    Rp[j] = fminf(fmaxf(rr * (1.0f / 255.0f), 0.0f), 1.0f);
                    Gp[j] = fminf(fmaxf(gg * (1.0f / 255.0f), 0.0f), 1.0f);
                    Bp[j] = fminf(fmaxf(bb * (1.0f / 255.0f), 0.0f), 1.0f);
                }
            }
            size_t off = img_base + (size_t)(row0 + r) * IMG_W + col;
            *(float4*)(out + off)          = ro;
            *(float4*)(out + off + CH)     = go;
            *(float4*)(out + off + 2 * CH) = bo;
        }
    }
}

extern "C" void kernel_launch(void* const* d_in, const int* in_sizes, int n_in,
                              void* d_out, int out_size)
{
    const float* img = (const float*)d_in[0];
    const int* quality = (const int*)d_in[1];
    float* out = (float*)d_out;

    cudaFuncSetAttribute(jpeg_kernel,
                         cudaFuncAttributeMaxDynamicSharedMemorySize,
                         SMEM_BYTES);

    dim3 grid(BATCH * (IMG_H / 8));  // 1024 CTAs
    jpeg_kernel<<<grid, NTHREADS, SMEM_BYTES>>>(img, quality, out);
}